// round 1
// baseline (speedup 1.0000x reference)
#include <cuda_runtime.h>
#include <cstdint>

// EmbeddingBag(mode='sum') over T tables.
// weights: [T, V, D] f32, lS_o: [T, B] i32 (bag start offsets), lS_i: [T, N] i32
// out: [T, B, D] f32
// T=26, V=200000, D=64, B=4096, L=20, N=B*L=81920

#define T_TABLES 26
#define V_VOCAB  200000
#define D_DIM    64
#define B_BATCH  4096
#define N_IDX    (4096 * 20)

__global__ __launch_bounds__(256)
void embbag_kernel(const float* __restrict__ W,
                   const int*   __restrict__ offs,
                   const int*   __restrict__ idx,
                   float*       __restrict__ out)
{
    const int warps_per_block = blockDim.x >> 5;
    const int bag = blockIdx.x * warps_per_block + (threadIdx.x >> 5);
    if (bag >= T_TABLES * B_BATCH) return;

    const int t = bag / B_BATCH;
    const int b = bag - t * B_BATCH;
    const int lane = threadIdx.x & 31;

    const int start = __ldg(offs + t * B_BATCH + b);
    const int end   = (b + 1 < B_BATCH) ? __ldg(offs + t * B_BATCH + b + 1) : N_IDX;

    const int* __restrict__ idx_t = idx + (size_t)t * N_IDX;
    const float2* __restrict__ Wt =
        reinterpret_cast<const float2*>(W + (size_t)t * V_VOCAB * D_DIM);

    float2 acc = make_float2(0.f, 0.f);

    int j = start;
    // Unroll x4: keep 4 independent row-gathers in flight per lane (MLP).
    for (; j + 4 <= end; j += 4) {
        const int r0 = __ldg(idx_t + j + 0);
        const int r1 = __ldg(idx_t + j + 1);
        const int r2 = __ldg(idx_t + j + 2);
        const int r3 = __ldg(idx_t + j + 3);
        const float2 v0 = __ldg(Wt + (size_t)r0 * 32 + lane);
        const float2 v1 = __ldg(Wt + (size_t)r1 * 32 + lane);
        const float2 v2 = __ldg(Wt + (size_t)r2 * 32 + lane);
        const float2 v3 = __ldg(Wt + (size_t)r3 * 32 + lane);
        acc.x += v0.x; acc.y += v0.y;
        acc.x += v1.x; acc.y += v1.y;
        acc.x += v2.x; acc.y += v2.y;
        acc.x += v3.x; acc.y += v3.y;
    }
    for (; j < end; ++j) {
        const int r = __ldg(idx_t + j);
        const float2 v = __ldg(Wt + (size_t)r * 32 + lane);
        acc.x += v.x; acc.y += v.y;
    }

    reinterpret_cast<float2*>(out)[(size_t)bag * 32 + lane] = acc;
}

extern "C" void kernel_launch(void* const* d_in, const int* in_sizes, int n_in,
                              void* d_out, int out_size)
{
    const float* weights = (const float*)d_in[0];
    const int*   lS_o    = (const int*)  d_in[1];
    const int*   lS_i    = (const int*)  d_in[2];
    float*       out     = (float*)d_out;

    const int total_bags = T_TABLES * B_BATCH;      // 106496
    const int threads = 256;                        // 8 warps/block
    const int blocks = (total_bags + 7) / 8;        // 13312

    embbag_kernel<<<blocks, threads>>>(weights, lS_o, lS_i, out);
}

// round 2
// speedup vs baseline: 1.0218x; 1.0218x over previous
#include <cuda_runtime.h>
#include <cstdint>

// EmbeddingBag(mode='sum') over T tables.
// weights: [T, V, D] f32, lS_o: [T, B] i32, lS_i: [T, N] i32 -> out: [T, B, D] f32
// T=26, V=200000, D=64, B=4096, L=20, N=81920
//
// Layout: 16-lane sub-warp per bag, float4 loads (one row = 16 lanes x 16B = 256B).
// Each warp handles 2 bags; unroll x5 keeps 10 rows (20 x 128B lines) in flight per warp.

#define T_TABLES 26
#define V_VOCAB  200000
#define D_DIM    64
#define B_BATCH  4096
#define N_IDX    (4096 * 20)

__global__ __launch_bounds__(256)
void embbag_kernel(const float* __restrict__ W,
                   const int*   __restrict__ offs,
                   const int*   __restrict__ idx,
                   float*       __restrict__ out)
{
    const int sub   = threadIdx.x >> 4;                 // 16 sub-warps / block
    const int lane4 = threadIdx.x & 15;                 // lane within sub-warp
    const int bag   = blockIdx.x * 16 + sub;
    if (bag >= T_TABLES * B_BATCH) return;

    const int t = bag / B_BATCH;
    const int b = bag - t * B_BATCH;

    const int start = __ldg(offs + t * B_BATCH + b);
    const int end   = (b + 1 < B_BATCH) ? __ldg(offs + t * B_BATCH + b + 1) : N_IDX;

    const int* __restrict__ idx_t = idx + (size_t)t * N_IDX;
    const float4* __restrict__ Wt =
        reinterpret_cast<const float4*>(W + (size_t)t * V_VOCAB * D_DIM);

    float4 acc = make_float4(0.f, 0.f, 0.f, 0.f);

    int j = start;
    // Unroll x5: 5 independent row-gathers in flight per sub-warp (10 per warp).
    for (; j + 5 <= end; j += 5) {
        const int r0 = __ldg(idx_t + j + 0);
        const int r1 = __ldg(idx_t + j + 1);
        const int r2 = __ldg(idx_t + j + 2);
        const int r3 = __ldg(idx_t + j + 3);
        const int r4 = __ldg(idx_t + j + 4);
        const float4 v0 = __ldg(Wt + (size_t)r0 * 16 + lane4);
        const float4 v1 = __ldg(Wt + (size_t)r1 * 16 + lane4);
        const float4 v2 = __ldg(Wt + (size_t)r2 * 16 + lane4);
        const float4 v3 = __ldg(Wt + (size_t)r3 * 16 + lane4);
        const float4 v4 = __ldg(Wt + (size_t)r4 * 16 + lane4);
        acc.x += v0.x; acc.y += v0.y; acc.z += v0.z; acc.w += v0.w;
        acc.x += v1.x; acc.y += v1.y; acc.z += v1.z; acc.w += v1.w;
        acc.x += v2.x; acc.y += v2.y; acc.z += v2.z; acc.w += v2.w;
        acc.x += v3.x; acc.y += v3.y; acc.z += v3.z; acc.w += v3.w;
        acc.x += v4.x; acc.y += v4.y; acc.z += v4.z; acc.w += v4.w;
    }
    for (; j < end; ++j) {
        const int r = __ldg(idx_t + j);
        const float4 v = __ldg(Wt + (size_t)r * 16 + lane4);
        acc.x += v.x; acc.y += v.y; acc.z += v.z; acc.w += v.w;
    }

    reinterpret_cast<float4*>(out)[(size_t)bag * 16 + lane4] = acc;
}

extern "C" void kernel_launch(void* const* d_in, const int* in_sizes, int n_in,
                              void* d_out, int out_size)
{
    const float* weights = (const float*)d_in[0];
    const int*   lS_o    = (const int*)  d_in[1];
    const int*   lS_i    = (const int*)  d_in[2];
    float*       out     = (float*)d_out;

    const int total_bags = T_TABLES * B_BATCH;      // 106496
    const int bags_per_block = 16;                  // 256 threads, 16-lane sub-warps
    const int blocks = (total_bags + bags_per_block - 1) / bags_per_block;  // 6656

    embbag_kernel<<<blocks, 256>>>(weights, lS_o, lS_i, out);
}

// round 3
// speedup vs baseline: 1.0284x; 1.0064x over previous
#include <cuda_runtime.h>
#include <cuda.h>
#include <cstdint>

// EmbeddingBag(mode='sum'), T=26 tables, V=200000, D=64, B=4096, L=20.
// weights: [T, V, D] f32  -> viewed as one 2D tensor [T*V, 64] for TMA gather4
// lS_o: [T, B] i32, lS_i: [T, N] i32, out: [T, B, D] f32

#define T_TABLES 26
#define V_VOCAB  200000
#define D_DIM    64
#define B_BATCH  4096
#define L_BAG    20
#define N_IDX    (B_BATCH * L_BAG)

#define BAGS_PER_CTA 8
#define THREADS_TMA  128
#define BAG_BYTES    (L_BAG * D_DIM * 4)   // 5120

// ---------- PTX helpers ----------
__device__ __forceinline__ uint32_t smem_u32(const void* p) {
    uint32_t a;
    asm("{ .reg .u64 t; cvta.to.shared.u64 t, %1; cvt.u32.u64 %0, t; }" : "=r"(a) : "l"(p));
    return a;
}

#define MBARRIER_INIT(addr, cnt) \
    asm volatile("mbarrier.init.shared.b64 [%0], %1;" :: "r"(addr), "r"((uint32_t)(cnt)) : "memory")

#define MBARRIER_EXPECT_TX(addr, bytes) \
    asm volatile("mbarrier.arrive.expect_tx.shared.b64 _, [%0], %1;" \
                 :: "r"(addr), "r"((uint32_t)(bytes)) : "memory")

#define FENCE_PROXY_ASYNC() asm volatile("fence.proxy.async.shared::cta;" ::: "memory")

#define MBARRIER_WAIT_PARITY(mbar_addr, parity) do {                                   \
    uint32_t _m = (mbar_addr); uint32_t _p = (parity); uint32_t _d;                    \
    asm volatile("{\n\t.reg .pred p;\n\t"                                              \
        "mbarrier.try_wait.parity.acquire.cta.shared::cta.b64 p, [%1], %2;\n\t"        \
        "selp.b32 %0, 1, 0, p;\n\t}" : "=r"(_d) : "r"(_m), "r"(_p) : "memory");        \
    if (!_d) {                                                                         \
        asm volatile("{\n\t.reg .pred P1;\n\t"                                         \
            "WL_%=:\n\t"                                                               \
            "mbarrier.try_wait.parity.acquire.cta.shared::cta.b64 P1, [%0], %1, 0x989680;\n\t" \
            "@P1 bra.uni WD_%=;\n\t"                                                   \
            "bra.uni WL_%=;\n\t"                                                       \
            "WD_%=:\n\t}" :: "r"(_m), "r"(_p) : "memory");                             \
    }                                                                                  \
} while (0)

__device__ __forceinline__ void tma_gather4(
    uint32_t dst_smem, const CUtensorMap* tmap,
    int col, int r0, int r1, int r2, int r3, uint32_t mbar)
{
    asm volatile(
        "cp.async.bulk.tensor.2d.shared::cta.global.tile::gather4.mbarrier::complete_tx::bytes "
        "[%0], [%1, {%2, %3, %4, %5, %6}], [%7];"
        :: "r"(dst_smem), "l"(tmap), "r"(col), "r"(r0), "r"(r1), "r"(r2), "r"(r3), "r"(mbar)
        : "memory");
}

// ---------- TMA gather4 kernel ----------
__global__ __launch_bounds__(THREADS_TMA)
void embbag_tma_kernel(const __grid_constant__ CUtensorMap tmap,
                       const int* __restrict__ offs,
                       const int* __restrict__ idx,
                       float*     __restrict__ out)
{
    __shared__ alignas(1024) float buf[BAGS_PER_CTA][L_BAG * D_DIM];   // 5120 B/bag = 40 KB
    __shared__ alignas(8) unsigned long long mb[BAGS_PER_CTA];

    const int tid  = threadIdx.x;
    const int wid  = tid >> 5;    // 4 warps, each owns bags 2*wid, 2*wid+1
    const int lane = tid & 31;

    if (lane == 0) {
        MBARRIER_INIT(smem_u32(&mb[2 * wid + 0]), 1);
        MBARRIER_INIT(smem_u32(&mb[2 * wid + 1]), 1);
        FENCE_PROXY_ASYNC();
    }
    __syncthreads();

    // Issue phase: both bags' gathers up front (10 gather4 = 10 KB in flight per warp)
    #pragma unroll
    for (int s = 0; s < 2; ++s) {
        const int slot = 2 * wid + s;
        const int bag  = blockIdx.x * BAGS_PER_CTA + slot;
        const int t = bag / B_BATCH;
        const int b = bag - t * B_BATCH;
        const int start = __ldg(offs + t * B_BATCH + b);

        int myrow = 0;
        if (lane < L_BAG)
            myrow = t * V_VOCAB + __ldg(idx + (size_t)t * N_IDX + start + lane);

        const uint32_t mbar = smem_u32(&mb[slot]);
        if (lane == 0) MBARRIER_EXPECT_TX(mbar, BAG_BYTES);

        #pragma unroll
        for (int g = 0; g < 5; ++g) {
            const int r0 = __shfl_sync(0xffffffffu, myrow, 4 * g + 0);
            const int r1 = __shfl_sync(0xffffffffu, myrow, 4 * g + 1);
            const int r2 = __shfl_sync(0xffffffffu, myrow, 4 * g + 2);
            const int r3 = __shfl_sync(0xffffffffu, myrow, 4 * g + 3);
            if (lane == 0) {
                tma_gather4(smem_u32(&buf[slot][g * 4 * D_DIM]), &tmap,
                            0, r0, r1, r2, r3, mbar);
            }
        }
    }

    // Consume phase
    #pragma unroll
    for (int s = 0; s < 2; ++s) {
        const int slot = 2 * wid + s;
        const int bag  = blockIdx.x * BAGS_PER_CTA + slot;

        MBARRIER_WAIT_PARITY(smem_u32(&mb[slot]), 0);

        const float2* p = reinterpret_cast<const float2*>(buf[slot]) + lane; // row r at p[r*32]
        float2 acc = make_float2(0.f, 0.f);
        #pragma unroll
        for (int r = 0; r < L_BAG; ++r) {
            const float2 v = p[r * 32];
            acc.x += v.x; acc.y += v.y;
        }
        reinterpret_cast<float2*>(out)[(size_t)bag * 32 + lane] = acc;
    }
}

// ---------- fallback LDG kernel (proven 80.6us) ----------
__global__ __launch_bounds__(256)
void embbag_ldg_kernel(const float* __restrict__ W,
                       const int*   __restrict__ offs,
                       const int*   __restrict__ idx,
                       float*       __restrict__ out)
{
    const int sub   = threadIdx.x >> 4;
    const int lane4 = threadIdx.x & 15;
    const int bag   = blockIdx.x * 16 + sub;
    if (bag >= T_TABLES * B_BATCH) return;

    const int t = bag / B_BATCH;
    const int b = bag - t * B_BATCH;
    const int start = __ldg(offs + t * B_BATCH + b);
    const int end   = (b + 1 < B_BATCH) ? __ldg(offs + t * B_BATCH + b + 1) : N_IDX;

    const int* __restrict__ idx_t = idx + (size_t)t * N_IDX;
    const float4* __restrict__ Wt =
        reinterpret_cast<const float4*>(W + (size_t)t * V_VOCAB * D_DIM);

    float4 acc = make_float4(0.f, 0.f, 0.f, 0.f);
    int j = start;
    for (; j + 5 <= end; j += 5) {
        const int r0 = __ldg(idx_t + j + 0);
        const int r1 = __ldg(idx_t + j + 1);
        const int r2 = __ldg(idx_t + j + 2);
        const int r3 = __ldg(idx_t + j + 3);
        const int r4 = __ldg(idx_t + j + 4);
        const float4 v0 = __ldg(Wt + (size_t)r0 * 16 + lane4);
        const float4 v1 = __ldg(Wt + (size_t)r1 * 16 + lane4);
        const float4 v2 = __ldg(Wt + (size_t)r2 * 16 + lane4);
        const float4 v3 = __ldg(Wt + (size_t)r3 * 16 + lane4);
        const float4 v4 = __ldg(Wt + (size_t)r4 * 16 + lane4);
        acc.x += v0.x; acc.y += v0.y; acc.z += v0.z; acc.w += v0.w;
        acc.x += v1.x; acc.y += v1.y; acc.z += v1.z; acc.w += v1.w;
        acc.x += v2.x; acc.y += v2.y; acc.z += v2.z; acc.w += v2.w;
        acc.x += v3.x; acc.y += v3.y; acc.z += v3.z; acc.w += v3.w;
        acc.x += v4.x; acc.y += v4.y; acc.z += v4.z; acc.w += v4.w;
    }
    for (; j < end; ++j) {
        const int r = __ldg(idx_t + j);
        const float4 v = __ldg(Wt + (size_t)r * 16 + lane4);
        acc.x += v.x; acc.y += v.y; acc.z += v.z; acc.w += v.w;
    }
    reinterpret_cast<float4*>(out)[(size_t)bag * 16 + lane4] = acc;
}

// ---------- host ----------
typedef CUresult (*EncodeTiledFn)(
    CUtensorMap*, CUtensorMapDataType, cuuint32_t, void*,
    const cuuint64_t*, const cuuint64_t*, const cuuint32_t*, const cuuint32_t*,
    CUtensorMapInterleave, CUtensorMapSwizzle, CUtensorMapL2promotion, CUtensorMapFloatOOBfill);

extern "C" void kernel_launch(void* const* d_in, const int* in_sizes, int n_in,
                              void* d_out, int out_size)
{
    const float* weights = (const float*)d_in[0];
    const int*   lS_o    = (const int*)  d_in[1];
    const int*   lS_i    = (const int*)  d_in[2];
    float*       out     = (float*)d_out;

    bool use_tma = false;
    CUtensorMap tmap;

    void* fp = nullptr;
    cudaDriverEntryPointQueryResult qr = cudaDriverEntryPointSymbolNotFound;
    cudaError_t e = cudaGetDriverEntryPointByVersion(
        "cuTensorMapEncodeTiled", &fp, 12000, cudaEnableDefault, &qr);
    if (e == cudaSuccess && fp != nullptr && qr == cudaDriverEntryPointSuccess) {
        EncodeTiledFn enc = (EncodeTiledFn)fp;
        cuuint64_t dims[2]    = {D_DIM, (cuuint64_t)T_TABLES * V_VOCAB};
        cuuint64_t strides[1] = {D_DIM * sizeof(float)};      // 256 B row stride
        cuuint32_t box[2]     = {D_DIM, 1};
        cuuint32_t estr[2]    = {1, 1};
        CUresult r = enc(&tmap, CU_TENSOR_MAP_DATA_TYPE_FLOAT32, 2, (void*)weights,
                         dims, strides, box, estr,
                         CU_TENSOR_MAP_INTERLEAVE_NONE, CU_TENSOR_MAP_SWIZZLE_NONE,
                         CU_TENSOR_MAP_L2_PROMOTION_L2_128B,
                         CU_TENSOR_MAP_FLOAT_OOB_FILL_NONE);
        if (r == CUDA_SUCCESS) use_tma = true;
    }

    const int total_bags = T_TABLES * B_BATCH;  // 106496

    if (use_tma) {
        const int blocks = total_bags / BAGS_PER_CTA;   // 13312
        embbag_tma_kernel<<<blocks, THREADS_TMA>>>(tmap, lS_o, lS_i, out);
    } else {
        const int blocks = (total_bags + 15) / 16;
        embbag_ldg_kernel<<<blocks, 256>>>(weights, lS_o, lS_i, out);
    }
}